// round 4
// baseline (speedup 1.0000x reference)
#include <cuda_runtime.h>

// GCMConv: gauge-covariant convolution on 8x8x16x16 lattice.
// x: (1, 16384, 8, 3, 3, 2) float32  [channels: 4 gauge links U_a, 4 fields w_c]
// weight: (4, 9, 33) float32
// out: (1, 16384, 8, 3, 3, 2): [U (copied), w_out]
//
// M-form with packed f32x2 FMA:
//   M_{uv} = sum_k c1_{uvk} T_k + c2_{uvk} T_k^dag + c3_{uv} I   (2 fma.f32x2 per elem per k)
//   w_out[u] = M_{u8} + sum_c w_c @ M_{uc} + w_c^dag @ M_{u,4+c}
// Scratch stores T packed (re,im) AND elementwise-conj (re,-im) so the dagger
// term is a pure f32x2 FMA with transposed indexing.

#define NS 16384

// Scratch layout, float2 elements, all [e_global * NS + site]:
//  k = 0..15:  e = k*18 + m      -> T_k[m]          (re, im)
//              e = k*18 + 9 + m  -> conj(T_k[m])    (re,-im)
//  own fields: e = 288 + c*9 + m -> w_c[m]          (re, im)
__device__ float2 g_T[(16 * 18 + 4 * 9) * NS];

typedef unsigned long long ull;

__device__ __forceinline__ ull pk2(float lo, float hi) {
    ull r;
    asm("mov.b64 %0, {%1, %2};" : "=l"(r) : "f"(lo), "f"(hi));
    return r;
}
__device__ __forceinline__ void upk2(float& lo, float& hi, ull v) {
    asm("mov.b64 {%0, %1}, %2;" : "=f"(lo), "=f"(hi) : "l"(v));
}
__device__ __forceinline__ ull fma2(ull a, ull b, ull c) {
    ull d;
    asm("fma.rn.f32x2 %0, %1, %2, %3;" : "=l"(d) : "l"(a), "l"(b), "l"(c));
    return d;
}

__global__ __launch_bounds__(256) void transport_kernel(const float* __restrict__ x) {
    int g = blockIdx.x * 256 + threadIdx.x;   // 0 .. 4*NS-1
    int site = g & (NS - 1);
    int a = g >> 14;                           // axis 0..3

    // periodic +1 neighbor; dims (8,8,16,16), strides (2048,256,16,1)
    int d3 = site & 15, d2 = (site >> 4) & 15, d1 = (site >> 8) & 7, d0 = (site >> 11) & 7;
    int nbr;
    if (a == 0)      nbr = site + ((((d0 + 1) & 7) - d0) << 11);
    else if (a == 1) nbr = site + ((((d1 + 1) & 7) - d1) << 8);
    else if (a == 2) nbr = site + ((((d2 + 1) & 15) - d2) << 4);
    else             nbr = site + (((d3 + 1) & 15) - d3);

    float Ur[3][3], Ui[3][3];
    {
        const float2* up = (const float2*)(x + site * 144 + a * 18);
#pragma unroll
        for (int m = 0; m < 9; m++) {
            float2 t = up[m];
            Ur[m / 3][m % 3] = t.x;
            Ui[m / 3][m % 3] = t.y;
        }
    }

#pragma unroll
    for (int c = 0; c < 4; c++) {
        float Wr[3][3], Wi[3][3];
        const float2* wp = (const float2*)(x + nbr * 144 + (4 + c) * 18);
#pragma unroll
        for (int m = 0; m < 9; m++) {
            float2 t = wp[m];
            Wr[m / 3][m % 3] = t.x;
            Wi[m / 3][m % 3] = t.y;
        }
        // t1 = U @ W
        float t1r[3][3], t1i[3][3];
#pragma unroll
        for (int i = 0; i < 3; i++)
#pragma unroll
            for (int kk = 0; kk < 3; kk++) {
                float cr = 0.f, ci = 0.f;
#pragma unroll
                for (int j = 0; j < 3; j++) {
                    cr += Ur[i][j] * Wr[j][kk] - Ui[i][j] * Wi[j][kk];
                    ci += Ur[i][j] * Wi[j][kk] + Ui[i][j] * Wr[j][kk];
                }
                t1r[i][kk] = cr;
                t1i[i][kk] = ci;
            }
        // T = t1 @ U^dag ; write T and conj(T)
        int ebase = (a * 4 + c) * 18;
#pragma unroll
        for (int i = 0; i < 3; i++)
#pragma unroll
            for (int kk = 0; kk < 3; kk++) {
                float cr = 0.f, ci = 0.f;
#pragma unroll
                for (int j = 0; j < 3; j++) {
                    float br = Ur[kk][j], bi = -Ui[kk][j];
                    cr += t1r[i][j] * br - t1i[i][j] * bi;
                    ci += t1r[i][j] * bi + t1i[i][j] * br;
                }
                g_T[(ebase + i * 3 + kk) * NS + site]     = make_float2(cr, ci);
                g_T[(ebase + 9 + i * 3 + kk) * NS + site] = make_float2(cr, -ci);
            }
    }

    // own-site field: thread (site, a) copies channel c = a
    {
        const float2* wp = (const float2*)(x + site * 144 + (4 + a) * 18);
#pragma unroll
        for (int m = 0; m < 9; m++)
            g_T[(288 + a * 9 + m) * NS + site] = wp[m];
    }
}

__global__ __launch_bounds__(128, 3) void contract_kernel(const float* __restrict__ x,
                                                          const float* __restrict__ weight,
                                                          float* __restrict__ out) {
    __shared__ ull wt2[297];  // [w*9 + v] = (c, c) packed, c = weight[u, v, w]

    int g = blockIdx.x * 128 + threadIdx.x;
    int site = g & (NS - 1);
    int u = g >> 14;  // whole block shares one u

    for (int s = threadIdx.x; s < 297; s += 128) {
        int v = s / 33, w = s % 33;
        float c = weight[u * 297 + s];
        wt2[w * 9 + v] = pk2(c, c);
    }
    __syncthreads();

    const ull* gt = reinterpret_cast<const ull*>(g_T);

    // copy gauge link channel u to output
    {
        const ull* src = reinterpret_cast<const ull*>(x + site * 144 + u * 18);
        ull* dst = reinterpret_cast<ull*>(out + site * 144 + u * 18);
#pragma unroll
        for (int m = 0; m < 9; m++) dst[m] = src[m];
    }

    float accr[3][3], acci[3][3];

    // ---------------- Pass A: v in {0,1,2,3,8} ----------------
    {
        ull M[5][9];
#pragma unroll
        for (int t = 0; t < 5; t++) {
            int v = (t < 4) ? t : 8;
            ull dg = wt2[32 * 9 + v] & 0xFFFFFFFFull;  // (c3, +0.0f)
#pragma unroll
            for (int m = 0; m < 9; m++) M[t][m] = 0ull;
            M[t][0] = dg; M[t][4] = dg; M[t][8] = dg;
        }

#pragma unroll 2
        for (int k = 0; k < 16; k++) {
            ull d[9], cj[9];
#pragma unroll
            for (int m = 0; m < 9; m++) d[m] = gt[(k * 18 + m) * NS + site];
#pragma unroll
            for (int m = 0; m < 9; m++) cj[m] = gt[(k * 18 + 9 + m) * NS + site];
#pragma unroll
            for (int t = 0; t < 5; t++) {
                int v = (t < 4) ? t : 8;
                ull a1 = wt2[k * 9 + v];
                ull a2 = wt2[(16 + k) * 9 + v];
#pragma unroll
                for (int i = 0; i < 3; i++)
#pragma unroll
                    for (int j = 0; j < 3; j++) {
                        M[t][i * 3 + j] = fma2(a1, d[i * 3 + j], M[t][i * 3 + j]);
                        M[t][i * 3 + j] = fma2(a2, cj[j * 3 + i], M[t][i * 3 + j]);
                    }
            }
        }

        // acc = M_8
#pragma unroll
        for (int i = 0; i < 3; i++)
#pragma unroll
            for (int j = 0; j < 3; j++)
                upk2(accr[i][j], acci[i][j], M[4][i * 3 + j]);

        // acc += w_c @ M_c
#pragma unroll
        for (int c = 0; c < 4; c++) {
            float wr[3][3], wi[3][3], mr[3][3], mi[3][3];
#pragma unroll
            for (int m = 0; m < 9; m++) {
                ull wv = gt[(288 + c * 9 + m) * NS + site];
                upk2(wr[m / 3][m % 3], wi[m / 3][m % 3], wv);
                upk2(mr[m / 3][m % 3], mi[m / 3][m % 3], M[c][m]);
            }
#pragma unroll
            for (int i = 0; i < 3; i++)
#pragma unroll
                for (int kk = 0; kk < 3; kk++) {
                    float cr = accr[i][kk], ci = acci[i][kk];
#pragma unroll
                    for (int j = 0; j < 3; j++) {
                        cr += wr[i][j] * mr[j][kk] - wi[i][j] * mi[j][kk];
                        ci += wr[i][j] * mi[j][kk] + wi[i][j] * mr[j][kk];
                    }
                    accr[i][kk] = cr; acci[i][kk] = ci;
                }
        }
    }

    // ---------------- Pass B: v in {4,5,6,7} ----------------
    {
        ull M[4][9];
#pragma unroll
        for (int t = 0; t < 4; t++) {
            ull dg = wt2[32 * 9 + 4 + t] & 0xFFFFFFFFull;
#pragma unroll
            for (int m = 0; m < 9; m++) M[t][m] = 0ull;
            M[t][0] = dg; M[t][4] = dg; M[t][8] = dg;
        }

#pragma unroll 2
        for (int k = 0; k < 16; k++) {
            ull d[9], cj[9];
#pragma unroll
            for (int m = 0; m < 9; m++) d[m] = gt[(k * 18 + m) * NS + site];
#pragma unroll
            for (int m = 0; m < 9; m++) cj[m] = gt[(k * 18 + 9 + m) * NS + site];
#pragma unroll
            for (int t = 0; t < 4; t++) {
                ull a1 = wt2[k * 9 + 4 + t];
                ull a2 = wt2[(16 + k) * 9 + 4 + t];
#pragma unroll
                for (int i = 0; i < 3; i++)
#pragma unroll
                    for (int j = 0; j < 3; j++) {
                        M[t][i * 3 + j] = fma2(a1, d[i * 3 + j], M[t][i * 3 + j]);
                        M[t][i * 3 + j] = fma2(a2, cj[j * 3 + i], M[t][i * 3 + j]);
                    }
            }
        }

        // acc += w_c^dag @ M_{4+c}
#pragma unroll
        for (int c = 0; c < 4; c++) {
            float wr[3][3], wi[3][3], mr[3][3], mi[3][3];
#pragma unroll
            for (int m = 0; m < 9; m++) {
                ull wv = gt[(288 + c * 9 + m) * NS + site];
                upk2(wr[m / 3][m % 3], wi[m / 3][m % 3], wv);
                upk2(mr[m / 3][m % 3], mi[m / 3][m % 3], M[c][m]);
            }
#pragma unroll
            for (int i = 0; i < 3; i++)
#pragma unroll
                for (int kk = 0; kk < 3; kk++) {
                    float cr = accr[i][kk], ci = acci[i][kk];
#pragma unroll
                    for (int j = 0; j < 3; j++) {
                        // conj(wc[j][i]) * M[j][kk]
                        cr += wr[j][i] * mr[j][kk] + wi[j][i] * mi[j][kk];
                        ci += wr[j][i] * mi[j][kk] - wi[j][i] * mr[j][kk];
                    }
                    accr[i][kk] = cr; acci[i][kk] = ci;
                }
        }
    }

    float2* dst = (float2*)(out + site * 144 + (4 + u) * 18);
#pragma unroll
    for (int i = 0; i < 3; i++)
#pragma unroll
        for (int j = 0; j < 3; j++)
            dst[i * 3 + j] = make_float2(accr[i][j], acci[i][j]);
}

extern "C" void kernel_launch(void* const* d_in, const int* in_sizes, int n_in,
                              void* d_out, int out_size) {
    const float* x = (const float*)d_in[0];
    const float* weight = (const float*)d_in[1];
    float* out = (float*)d_out;

    transport_kernel<<<4 * NS / 256, 256>>>(x);
    contract_kernel<<<4 * NS / 128, 128>>>(x, weight, out);
}